// round 13
// baseline (speedup 1.0000x reference)
#include <cuda_runtime.h>
#include <cuda_fp16.h>
#include <math.h>
#include <stdint.h>

#define Bb 2
#define Nn 5
#define Kk 5
#define Qq 75
#define Tt 196
#define Cc 384
#define Ssz (Kk*Tt)        /* 980 */
#define MQ  (Qq*Tt)        /* 14700 rows per batch */
#define MQP 14848          /* padded M per batch (58*256) */
#define SSP 1024           /* padded S per (b,n) */
#define MTILES 58          /* per batch, tile 256 */
#define NTILES 8           /* 1024/128 */
#define KCH 6              /* 384/64 */
#define NSTEPS (NTILES*KCH)
#define RMSTRIDE 14720
#define TEMPF 10.0f

// dynamic smem layout (bytes, after 1KB alignment)
#define OFF_A  0                 /* A resident: 256 rows x 768B = 196608 */
#define OFF_B0 196608            /* B stage: 128 rows x 128B = 16384    */
#define OFF_B1 212992
#define SMEM_BYTES (229376 + 1024)

// ---------------- scratch (device globals: allocation-guard safe) ------------
__device__ __align__(16) __half g_Qh[Bb*MQP*Cc];      // [b][m(pad)][c] fp16 normalized
__device__ __align__(16) __half g_Sh[Bb*Nn*SSP*Cc];   // [bn][s(pad)][c]
__device__ __align__(16) float g_rowmax[Bb*Nn*RMSTRIDE];

// ---------------- helpers ----------------------------------------------------
__device__ __forceinline__ uint32_t smem_u32(const void* p) {
    uint32_t a;
    asm("{ .reg .u64 t; cvta.to.shared.u64 t, %1; cvt.u32.u64 %0, t; }" : "=r"(a) : "l"(p));
    return a;
}
__device__ __forceinline__ void cp16(uint32_t saddr, const void* g) {
    asm volatile("cp.async.cg.shared.global [%0], [%1], 16;" :: "r"(saddr), "l"(g));
}
__device__ __forceinline__ void cp_commit() {
    asm volatile("cp.async.commit_group;" ::: "memory");
}
__device__ __forceinline__ void cp_wait1() {
    asm volatile("cp.async.wait_group 1;" ::: "memory");
}
__device__ __forceinline__ void cp_wait0() {
    asm volatile("cp.async.wait_group 0;" ::: "memory");
}
__device__ __forceinline__ void ldsm4(uint32_t* r, uint32_t addr) {
    asm volatile("ldmatrix.sync.aligned.m8n8.x4.shared.b16 {%0,%1,%2,%3}, [%4];"
        : "=r"(r[0]), "=r"(r[1]), "=r"(r[2]), "=r"(r[3]) : "r"(addr));
}
__device__ __forceinline__ void mma16816(float* c, const uint32_t* a,
                                         uint32_t b0, uint32_t b1) {
    asm("mma.sync.aligned.m16n8k16.row.col.f32.f16.f16.f32 "
        "{%0,%1,%2,%3}, {%4,%5,%6,%7}, {%8,%9}, {%0,%1,%2,%3};"
        : "+f"(c[0]), "+f"(c[1]), "+f"(c[2]), "+f"(c[3])
        : "r"(a[0]), "r"(a[1]), "r"(a[2]), "r"(a[3]), "r"(b0), "r"(b1));
}
__device__ __forceinline__ uint32_t h2bits(float x, float y) {
    __half2 h = __floats2half2_rn(x, y);
    return *(uint32_t*)&h;
}

// ---------------- row L2 normalization -> fp16 -------------------------------
__device__ __forceinline__ void norm_rows_h(const float* __restrict__ in,
                                            __half* __restrict__ out,
                                            int rows, int inner, int pad_stride,
                                            float eps) {
    int row = blockIdx.x * 4 + (threadIdx.x >> 5);
    if (row >= rows) return;
    int lane = threadIdx.x & 31;
    int blk = row / inner, r = row - blk * inner;
    const float4* ip = (const float4*)(in + (size_t)row * Cc) + lane;
    float4 v0 = ip[0], v1 = ip[32], v2 = ip[64];
    float ss = v0.x*v0.x + v0.y*v0.y + v0.z*v0.z + v0.w*v0.w
             + v1.x*v1.x + v1.y*v1.y + v1.z*v1.z + v1.w*v1.w
             + v2.x*v2.x + v2.y*v2.y + v2.z*v2.z + v2.w*v2.w;
    #pragma unroll
    for (int o = 16; o; o >>= 1) ss += __shfl_xor_sync(0xffffffffu, ss, o);
    float s = 1.0f / fmaxf(sqrtf(ss), eps);
    uint2* op = (uint2*)(out + ((size_t)blk * pad_stride + r) * Cc);
    uint2 u0, u1, u2;
    u0.x = h2bits(v0.x*s, v0.y*s); u0.y = h2bits(v0.z*s, v0.w*s);
    u1.x = h2bits(v1.x*s, v1.y*s); u1.y = h2bits(v1.z*s, v1.w*s);
    u2.x = h2bits(v2.x*s, v2.y*s); u2.y = h2bits(v2.z*s, v2.w*s);
    op[lane] = u0; op[lane + 32] = u1; op[lane + 64] = u2;
}
__global__ void norm_q_kernel(const float* __restrict__ in) {
    norm_rows_h(in, g_Qh, Bb*MQ, MQ, MQP, 1e-8f);
}
__global__ void norm_s_kernel(const float* __restrict__ in) {
    norm_rows_h(in, g_Sh, Bb*Nn*Ssz, Ssz, SSP, 1e-8f);
}

// ---------------- fp16 mma.sync GEMM + fused max-over-s ----------------------
// Grid (58 Mtiles, 10 bn), 256 threads = 8 warps as 4(m)x2(n), warp tile 64x64.
// A (256 x 384 fp16, 192KB) resident in SMEM for the whole CTA; only B is
// streamed (k64 chunks of the current 128-col s-tile), double-buffered.
__global__ __launch_bounds__(256, 1) void sim_mma_kernel() {
    extern __shared__ char dsm_raw[];
    const uint32_t base = (smem_u32(dsm_raw) + 1023) & ~1023u;

    const int tid = threadIdx.x;
    const int wid = tid >> 5, lane = tid & 31;
    const int wm = wid >> 1, wn = wid & 1;
    const int g = lane >> 2, q = lane & 3;
    const int lr = lane & 15;              // ldmatrix row-in-16
    const int lk = (lane >> 4) * 16;       // ldmatrix k-half byte offset
    const uint32_t sw = ((uint32_t)(lane & 7)) << 4;
    const int m0 = blockIdx.x * 256;
    const int bn = blockIdx.y;
    const int b  = bn / Nn;

    const __half* Ag = g_Qh + ((size_t)b * MQP + m0) * Cc;
    const __half* Sg = g_Sh + (size_t)bn * SSP * Cc;

    const uint32_t abase = base + OFF_A;
    const uint32_t bbuf[2] = { base + OFF_B0, base + OFF_B1 };
    float* red = (float*)(dsm_raw + (base - smem_u32(dsm_raw)) + OFF_A);

    float rmax[8];
    #pragma unroll
    for (int i = 0; i < 8; i++) rmax[i] = -1e30f;

    // ---- prologue: stage full A (256 rows x 48 16B-units) + B step 0 --------
    {
        #pragma unroll
        for (int it = 0; it < 48; it++) {
            int task = it * 256 + tid;
            int row = task / 48, u = task - row * 48;
            cp16(abase + row*768 + (u >> 3)*128 + (((u & 7)*16) ^ ((row & 7) << 4)),
                 Ag + (size_t)row * Cc + u*8);
        }
        #pragma unroll
        for (int it = 0; it < 4; it++) {
            int task = it * 256 + tid;
            int row = task >> 3, u = task & 7;
            cp16(bbuf[0] + row*128 + ((u*16) ^ ((row & 7) << 4)),
                 Sg + (size_t)row * Cc + u*8);
        }
        cp_commit();   // group: A + B(step 0)
    }

    float acc[4][8][4];

    for (int step = 0; step < NSTEPS; step++) {
        const int nt = step / KCH, kc = step - nt * KCH;
        const int cur = step & 1;

        // ---- prefetch B for step+1 ----
        if (step + 1 < NSTEPS) {
            const int nt1 = (step + 1) / KCH, kc1 = (step + 1) - nt1 * KCH;
            const __half* Bsrc = Sg + (size_t)(nt1 * 128) * Cc + kc1 * 64;
            const uint32_t dst = bbuf[cur ^ 1];
            #pragma unroll
            for (int it = 0; it < 4; it++) {
                int task = it * 256 + tid;
                int row = task >> 3, u = task & 7;
                cp16(dst + row*128 + ((u*16) ^ ((row & 7) << 4)),
                     Bsrc + (size_t)row * Cc + u*8);
            }
            cp_commit();
            cp_wait1();
        } else {
            cp_wait0();
        }
        __syncthreads();

        if (kc == 0) {
            #pragma unroll
            for (int fm = 0; fm < 4; fm++)
                #pragma unroll
                for (int fn = 0; fn < 8; fn++)
                    #pragma unroll
                    for (int j = 0; j < 4; j++) acc[fm][fn][j] = 0.f;
        }

        // ---- compute: 4 k16 steps on resident A + B buf cur ----
        const uint32_t Abase = abase + (uint32_t)(wm*64 + lr) * 768 + (uint32_t)kc * 128;
        const uint32_t Bbase = bbuf[cur] + (uint32_t)(wn*64 + lr) * 128;
        #pragma unroll
        for (int kk = 0; kk < 4; kk++) {
            const uint32_t ako = ((uint32_t)(kk*32 + lk)) ^ sw;
            uint32_t afr[4][4], bfr[4][4];
            #pragma unroll
            for (int fm = 0; fm < 4; fm++)
                ldsm4(afr[fm], Abase + fm*(16*768) + ako);
            #pragma unroll
            for (int fb = 0; fb < 4; fb++)
                ldsm4(bfr[fb], Bbase + fb*(16*128) + ako);
            #pragma unroll
            for (int fm = 0; fm < 4; fm++)
                #pragma unroll
                for (int fn = 0; fn < 8; fn++)
                    mma16816(acc[fm][fn], afr[fm],
                             bfr[fn >> 1][fn & 1], bfr[fn >> 1][(fn & 1) + 2]);
        }
        __syncthreads();

        // ---- tile done: fold into running row maxes (mask s >= Ssz) ----
        if (kc == KCH - 1) {
            const int s0 = nt * 128;
            #pragma unroll
            for (int fn = 0; fn < 8; fn++) {
                int sc = s0 + wn*64 + fn*8 + q*2;
                bool v0 = (sc < Ssz), v1 = (sc + 1 < Ssz);
                #pragma unroll
                for (int fm = 0; fm < 4; fm++) {
                    if (v0) {
                        rmax[fm*2+0] = fmaxf(rmax[fm*2+0], acc[fm][fn][0]);
                        rmax[fm*2+1] = fmaxf(rmax[fm*2+1], acc[fm][fn][2]);
                    }
                    if (v1) {
                        rmax[fm*2+0] = fmaxf(rmax[fm*2+0], acc[fm][fn][1]);
                        rmax[fm*2+1] = fmaxf(rmax[fm*2+1], acc[fm][fn][3]);
                    }
                }
            }
        }
    }

    // ---- reduce across the 4 quad lanes (same row), then across 2 n-warps ----
    #pragma unroll
    for (int i = 0; i < 8; i++) {
        float v = rmax[i];
        v = fmaxf(v, __shfl_xor_sync(0xffffffffu, v, 1));
        v = fmaxf(v, __shfl_xor_sync(0xffffffffu, v, 2));
        rmax[i] = v;
    }
    __syncthreads();               // all ldsm reads of A done; reuse A region
    if (q == 0) {
        #pragma unroll
        for (int fm = 0; fm < 4; fm++) {
            red[wn*256 + wm*64 + fm*16 + g]     = rmax[fm*2+0];
            red[wn*256 + wm*64 + fm*16 + g + 8] = rmax[fm*2+1];
        }
    }
    __syncthreads();
    {
        int m = m0 + tid;
        if (m < MQ) {
            float v = fmaxf(red[tid], red[256 + tid]);
            g_rowmax[(size_t)bn * RMSTRIDE + m] = v;
        }
    }
}

// ---------------- mean over t ------------------------------------------------
__global__ void reduce_kernel(float* __restrict__ out) {
    int idx = blockIdx.x;                 // (b*Qq+q)*Nn + n
    int n  = idx % Nn;
    int bq = idx / Nn;
    int b  = bq / Qq, q = bq % Qq;
    const float* rm = g_rowmax + (size_t)(b*Nn + n) * RMSTRIDE + (size_t)q * Tt;
    int tid = threadIdx.x;                // 64 threads
    float s = 0.f;
    for (int t = tid; t < Tt; t += 64) s += rm[t];
    #pragma unroll
    for (int o = 16; o; o >>= 1) s += __shfl_xor_sync(0xffffffffu, s, o);
    __shared__ float sm[2];
    if ((tid & 31) == 0) sm[tid >> 5] = s;
    __syncthreads();
    if (tid == 0) out[idx] = (sm[0] + sm[1]) / (float)Tt;
}

// ---------------- classifier branch ------------------------------------------
__global__ void cls_kernel(const float* __restrict__ xs,
                           const float* __restrict__ xq,
                           float* __restrict__ out) {
    int bq = blockIdx.x;
    int b = bq / Qq, q = bq % Qq;
    int tid = threadIdx.x;                 // 128 threads
    int lane = tid & 31, wid = tid >> 5;
    __shared__ float sm[8];
    __shared__ float s_sqq;

    const float* xqr = xq + (size_t)(b*Qq + q) * Cc;
    float qv[3];
    float sqq = 0.f;
    #pragma unroll
    for (int j = 0; j < 3; j++) { qv[j] = xqr[tid + 128*j]; sqq += qv[j]*qv[j]; }
    float r = sqq;
    #pragma unroll
    for (int o = 16; o; o >>= 1) r += __shfl_xor_sync(0xffffffffu, r, o);
    if (lane == 0) sm[wid] = r;
    __syncthreads();
    if (tid == 0) s_sqq = sm[0] + sm[1] + sm[2] + sm[3];
    __syncthreads();

    for (int n = 0; n < Nn; n++) {
        float spp = 0.f, sqp = 0.f;
        #pragma unroll
        for (int j = 0; j < 3; j++) {
            int c = tid + 128*j;
            const float* xsr = xs + (size_t)(b*Nn + n) * Kk * Cc + c;
            float pv = 0.f;
            #pragma unroll
            for (int k = 0; k < Kk; k++) pv += xsr[(size_t)k*Cc];
            pv *= 0.2f;
            spp += pv*pv;
            sqp += qv[j]*pv;
        }
        float a = spp, d = sqp;
        #pragma unroll
        for (int o = 16; o; o >>= 1) {
            a += __shfl_xor_sync(0xffffffffu, a, o);
            d += __shfl_xor_sync(0xffffffffu, d, o);
        }
        if (lane == 0) { sm[wid] = a; sm[4 + wid] = d; }
        __syncthreads();
        if (tid == 0) {
            float PP = sm[0] + sm[1] + sm[2] + sm[3];
            float QP = sm[4] + sm[5] + sm[6] + sm[7];
            float denom = fmaxf(sqrtf(s_sqq), 1e-12f) * fmaxf(sqrtf(PP), 1e-12f);
            out[(size_t)Bb*Qq*Nn + (size_t)(b*Qq + q)*Nn + n] = TEMPF * QP / denom;
        }
        __syncthreads();
    }
}

// -----------------------------------------------------------------------------
extern "C" void kernel_launch(void* const* d_in, const int* in_sizes, int n_in,
                              void* d_out, int out_size) {
    const float *fs = nullptr, *fq = nullptr, *xs = nullptr, *xq = nullptr;
    for (int i = 0; i < n_in; i++) {
        long long sz = in_sizes[i];
        if      (sz == (long long)Bb*Nn*Kk*Tt*Cc) fs = (const float*)d_in[i];
        else if (sz == (long long)Bb*Qq*Tt*Cc)    fq = (const float*)d_in[i];
        else if (sz == (long long)Bb*Nn*Kk*Cc)    xs = (const float*)d_in[i];
        else if (sz == (long long)Bb*Qq*Cc)       xq = (const float*)d_in[i];
    }
    float* out = (float*)d_out;

    cudaFuncSetAttribute(sim_mma_kernel,
                         cudaFuncAttributeMaxDynamicSharedMemorySize, SMEM_BYTES);

    norm_q_kernel<<<(Bb*MQ + 3) / 4, 128>>>(fq);
    norm_s_kernel<<<(Bb*Nn*Ssz + 3) / 4, 128>>>(fs);
    sim_mma_kernel<<<dim3(MTILES, Bb*Nn), 256, SMEM_BYTES>>>();
    reduce_kernel<<<Bb*Qq*Nn, 64>>>(out);
    cls_kernel<<<Bb*Qq, 128>>>(xs, xq, out);
}

// round 14
// speedup vs baseline: 1.5891x; 1.5891x over previous
#include <cuda_runtime.h>
#include <cuda_fp16.h>
#include <math.h>
#include <stdint.h>

#define Bb 2
#define Nn 5
#define Kk 5
#define Qq 75
#define Tt 196
#define Cc 384
#define Ssz (Kk*Tt)        /* 980 */
#define MQ  (Qq*Tt)        /* 14700 rows per batch */
#define MQP 14848          /* padded M per batch (58*256) */
#define SSP 1024           /* padded S per (b,n) */
#define MTILES 58          /* per batch, tile 256 */
#define NTILES 8           /* 1024/128 */
#define KCH 6              /* 384/64 */
#define RMSTRIDE 14720
#define TEMPF 10.0f

// dynamic smem: 4 pipeline stages of (A 32KB + B 16KB) + reduction scratch
#define STG_BYTES 49152
#define OFF_RED   196608
#define SMEM_BYTES (196608 + 2048 + 1024)

// ---------------- scratch (device globals: allocation-guard safe) ------------
__device__ __align__(16) __half g_Qh[Bb*MQP*Cc];      // [b][m(pad)][c] fp16 normalized
__device__ __align__(16) __half g_Sh[Bb*Nn*SSP*Cc];   // [bn][s(pad)][c]
__device__ __align__(16) float g_rowmax[Bb*Nn*RMSTRIDE];

// ---------------- helpers ----------------------------------------------------
__device__ __forceinline__ uint32_t smem_u32(const void* p) {
    uint32_t a;
    asm("{ .reg .u64 t; cvta.to.shared.u64 t, %1; cvt.u32.u64 %0, t; }" : "=r"(a) : "l"(p));
    return a;
}
__device__ __forceinline__ void cp16(uint32_t saddr, const void* g) {
    asm volatile("cp.async.cg.shared.global [%0], [%1], 16;" :: "r"(saddr), "l"(g));
}
__device__ __forceinline__ void cp_commit() {
    asm volatile("cp.async.commit_group;" ::: "memory");
}
__device__ __forceinline__ void cp_wait2() {
    asm volatile("cp.async.wait_group 2;" ::: "memory");
}
__device__ __forceinline__ void cp_wait1() {
    asm volatile("cp.async.wait_group 1;" ::: "memory");
}
__device__ __forceinline__ void cp_wait0() {
    asm volatile("cp.async.wait_group 0;" ::: "memory");
}
__device__ __forceinline__ void ldsm4(uint32_t* r, uint32_t addr) {
    asm volatile("ldmatrix.sync.aligned.m8n8.x4.shared.b16 {%0,%1,%2,%3}, [%4];"
        : "=r"(r[0]), "=r"(r[1]), "=r"(r[2]), "=r"(r[3]) : "r"(addr));
}
__device__ __forceinline__ void mma16816(float* c, const uint32_t* a,
                                         uint32_t b0, uint32_t b1) {
    asm("mma.sync.aligned.m16n8k16.row.col.f32.f16.f16.f32 "
        "{%0,%1,%2,%3}, {%4,%5,%6,%7}, {%8,%9}, {%0,%1,%2,%3};"
        : "+f"(c[0]), "+f"(c[1]), "+f"(c[2]), "+f"(c[3])
        : "r"(a[0]), "r"(a[1]), "r"(a[2]), "r"(a[3]), "r"(b0), "r"(b1));
}
__device__ __forceinline__ uint32_t h2bits(float x, float y) {
    __half2 h = __floats2half2_rn(x, y);
    return *(uint32_t*)&h;
}

// ---------------- row L2 normalization -> fp16 -------------------------------
__device__ __forceinline__ void norm_rows_h(const float* __restrict__ in,
                                            __half* __restrict__ out,
                                            int rows, int inner, int pad_stride,
                                            float eps) {
    int row = blockIdx.x * 4 + (threadIdx.x >> 5);
    if (row >= rows) return;
    int lane = threadIdx.x & 31;
    int blk = row / inner, r = row - blk * inner;
    const float4* ip = (const float4*)(in + (size_t)row * Cc) + lane;
    float4 v0 = ip[0], v1 = ip[32], v2 = ip[64];
    float ss = v0.x*v0.x + v0.y*v0.y + v0.z*v0.z + v0.w*v0.w
             + v1.x*v1.x + v1.y*v1.y + v1.z*v1.z + v1.w*v1.w
             + v2.x*v2.x + v2.y*v2.y + v2.z*v2.z + v2.w*v2.w;
    #pragma unroll
    for (int o = 16; o; o >>= 1) ss += __shfl_xor_sync(0xffffffffu, ss, o);
    float s = 1.0f / fmaxf(sqrtf(ss), eps);
    uint2* op = (uint2*)(out + ((size_t)blk * pad_stride + r) * Cc);
    uint2 u0, u1, u2;
    u0.x = h2bits(v0.x*s, v0.y*s); u0.y = h2bits(v0.z*s, v0.w*s);
    u1.x = h2bits(v1.x*s, v1.y*s); u1.y = h2bits(v1.z*s, v1.w*s);
    u2.x = h2bits(v2.x*s, v2.y*s); u2.y = h2bits(v2.z*s, v2.w*s);
    op[lane] = u0; op[lane + 32] = u1; op[lane + 64] = u2;
}
__global__ void norm_q_kernel(const float* __restrict__ in) {
    norm_rows_h(in, g_Qh, Bb*MQ, MQ, MQP, 1e-8f);
}
__global__ void norm_s_kernel(const float* __restrict__ in) {
    norm_rows_h(in, g_Sh, Bb*Nn*Ssz, Ssz, SSP, 1e-8f);
}

// stage chunk (ntx, kcx) into pipeline stage stg: A 256x64h + B 128x64h, SW128
#define STAGE(stg, ntx, kcx) do {                                              \
    const __half* Asrc_ = Ag + (size_t)(kcx) * 64;                             \
    const __half* Bsrc_ = Sg + (size_t)((ntx) * 128) * Cc + (size_t)(kcx) * 64;\
    const uint32_t da_ = base + (uint32_t)(stg) * STG_BYTES;                   \
    const uint32_t db_ = da_ + 32768;                                          \
    _Pragma("unroll")                                                          \
    for (int it = 0; it < 8; it++) {                                           \
        int task = it * 256 + tid;                                             \
        int row = task >> 3, u = task & 7;                                     \
        cp16(da_ + row*128 + ((u*16) ^ ((row & 7) << 4)),                      \
             Asrc_ + (size_t)row * Cc + u*8);                                  \
    }                                                                          \
    _Pragma("unroll")                                                          \
    for (int it = 0; it < 4; it++) {                                           \
        int task = it * 256 + tid;                                             \
        int row = task >> 3, u = task & 7;                                     \
        cp16(db_ + row*128 + ((u*16) ^ ((row & 7) << 4)),                      \
             Bsrc_ + (size_t)row * Cc + u*8);                                  \
    }                                                                          \
    cp_commit();                                                               \
} while (0)

// ---------------- fp16 mma.sync GEMM + fused max-over-s ----------------------
// Grid (58 Mtiles, 10 bn), 256 threads = 8 warps as 4(m)x2(n), warp tile 64x64.
// 4-stage cp.async pipeline, lookahead 2 chunks, ONE __syncthreads per chunk.
__global__ __launch_bounds__(256, 1) void sim_mma_kernel() {
    extern __shared__ char dsm_raw[];
    const uint32_t base = (smem_u32(dsm_raw) + 1023) & ~1023u;

    const int tid = threadIdx.x;
    const int wid = tid >> 5, lane = tid & 31;
    const int wm = wid >> 1, wn = wid & 1;
    const int g = lane >> 2, q = lane & 3;
    const int lr = lane & 15;              // ldmatrix row-in-16
    const int lk = (lane >> 4) * 16;       // ldmatrix k-half byte offset
    const uint32_t sw = ((uint32_t)(lane & 7)) << 4;
    const int m0 = blockIdx.x * 256;
    const int bn = blockIdx.y;
    const int b  = bn / Nn;

    const __half* Ag = g_Qh + ((size_t)b * MQP + m0) * Cc;
    const __half* Sg = g_Sh + (size_t)bn * SSP * Cc;

    float* red = (float*)(dsm_raw + (base - smem_u32(dsm_raw)) + OFF_RED);

    float rmax[8];
    #pragma unroll
    for (int i = 0; i < 8; i++) rmax[i] = -1e30f;

    // ---- prologue: stage chunks 0 and 1 ----
    STAGE(0, 0, 0);
    STAGE(1, 0, 1);

    for (int nt = 0; nt < NTILES; nt++) {
        float acc[4][8][4];
        #pragma unroll
        for (int fm = 0; fm < 4; fm++)
            #pragma unroll
            for (int fn = 0; fn < 8; fn++)
                #pragma unroll
                for (int j = 0; j < 4; j++) acc[fm][fn][j] = 0.f;

        #pragma unroll
        for (int kc = 0; kc < KCH; kc++) {
            const int step = nt * KCH + kc;
            const int s = step & 3;

            // ---- prefetch chunk step+2 (crosses n-tile boundary) ----
            {
                int kc2 = kc + 2, nt2 = nt;
                if (kc2 >= KCH) { kc2 -= KCH; nt2++; }
                if (nt2 < NTILES) {
                    STAGE((step + 2) & 3, nt2, kc2);
                    cp_wait2();
                } else if (kc == KCH - 2) {
                    cp_wait1();
                } else {
                    cp_wait0();
                }
            }
            __syncthreads();   // single barrier per chunk

            // ---- compute: 4 k16 steps on stage s ----
            const uint32_t Abase = base + (uint32_t)s * STG_BYTES
                                 + (uint32_t)(wm*64 + lr) * 128;
            const uint32_t Bbase = base + (uint32_t)s * STG_BYTES + 32768
                                 + (uint32_t)(wn*64 + lr) * 128;
            #pragma unroll
            for (int kk = 0; kk < 4; kk++) {
                const uint32_t ko = ((uint32_t)(kk*32 + lk)) ^ sw;
                uint32_t afr[4][4], bfr[4][4];
                #pragma unroll
                for (int fm = 0; fm < 4; fm++)
                    ldsm4(afr[fm], Abase + fm*(16*128) + ko);
                #pragma unroll
                for (int fb = 0; fb < 4; fb++)
                    ldsm4(bfr[fb], Bbase + fb*(16*128) + ko);
                #pragma unroll
                for (int fm = 0; fm < 4; fm++)
                    #pragma unroll
                    for (int fn = 0; fn < 8; fn++)
                        mma16816(acc[fm][fn], afr[fm],
                                 bfr[fn >> 1][fn & 1], bfr[fn >> 1][(fn & 1) + 2]);
            }
        }

        // ---- tile done: fold into running row maxes (mask s >= Ssz) ----
        {
            const int s0 = nt * 128;
            #pragma unroll
            for (int fn = 0; fn < 8; fn++) {
                int sc = s0 + wn*64 + fn*8 + q*2;
                bool v0 = (sc < Ssz), v1 = (sc + 1 < Ssz);
                #pragma unroll
                for (int fm = 0; fm < 4; fm++) {
                    if (v0) {
                        rmax[fm*2+0] = fmaxf(rmax[fm*2+0], acc[fm][fn][0]);
                        rmax[fm*2+1] = fmaxf(rmax[fm*2+1], acc[fm][fn][2]);
                    }
                    if (v1) {
                        rmax[fm*2+0] = fmaxf(rmax[fm*2+0], acc[fm][fn][1]);
                        rmax[fm*2+1] = fmaxf(rmax[fm*2+1], acc[fm][fn][3]);
                    }
                }
            }
        }
    }

    // ---- reduce across the 4 quad lanes (same row), then across 2 n-warps ----
    #pragma unroll
    for (int i = 0; i < 8; i++) {
        float v = rmax[i];
        v = fmaxf(v, __shfl_xor_sync(0xffffffffu, v, 1));
        v = fmaxf(v, __shfl_xor_sync(0xffffffffu, v, 2));
        rmax[i] = v;
    }
    __syncthreads();
    if (q == 0) {
        #pragma unroll
        for (int fm = 0; fm < 4; fm++) {
            red[wn*256 + wm*64 + fm*16 + g]     = rmax[fm*2+0];
            red[wn*256 + wm*64 + fm*16 + g + 8] = rmax[fm*2+1];
        }
    }
    __syncthreads();
    {
        int m = m0 + tid;
        if (m < MQ) {
            float v = fmaxf(red[tid], red[256 + tid]);
            g_rowmax[(size_t)bn * RMSTRIDE + m] = v;
        }
    }
}

// ---------------- mean over t ------------------------------------------------
__global__ void reduce_kernel(float* __restrict__ out) {
    int idx = blockIdx.x;                 // (b*Qq+q)*Nn + n
    int n  = idx % Nn;
    int bq = idx / Nn;
    int b  = bq / Qq, q = bq % Qq;
    const float* rm = g_rowmax + (size_t)(b*Nn + n) * RMSTRIDE + (size_t)q * Tt;
    int tid = threadIdx.x;                // 64 threads
    float s = 0.f;
    for (int t = tid; t < Tt; t += 64) s += rm[t];
    #pragma unroll
    for (int o = 16; o; o >>= 1) s += __shfl_xor_sync(0xffffffffu, s, o);
    __shared__ float sm[2];
    if ((tid & 31) == 0) sm[tid >> 5] = s;
    __syncthreads();
    if (tid == 0) out[idx] = (sm[0] + sm[1]) / (float)Tt;
}

// ---------------- classifier branch ------------------------------------------
__global__ void cls_kernel(const float* __restrict__ xs,
                           const float* __restrict__ xq,
                           float* __restrict__ out) {
    int bq = blockIdx.x;
    int b = bq / Qq, q = bq % Qq;
    int tid = threadIdx.x;                 // 128 threads
    int lane = tid & 31, wid = tid >> 5;
    __shared__ float sm[8];
    __shared__ float s_sqq;

    const float* xqr = xq + (size_t)(b*Qq + q) * Cc;
    float qv[3];
    float sqq = 0.f;
    #pragma unroll
    for (int j = 0; j < 3; j++) { qv[j] = xqr[tid + 128*j]; sqq += qv[j]*qv[j]; }
    float r = sqq;
    #pragma unroll
    for (int o = 16; o; o >>= 1) r += __shfl_xor_sync(0xffffffffu, r, o);
    if (lane == 0) sm[wid] = r;
    __syncthreads();
    if (tid == 0) s_sqq = sm[0] + sm[1] + sm[2] + sm[3];
    __syncthreads();

    for (int n = 0; n < Nn; n++) {
        float spp = 0.f, sqp = 0.f;
        #pragma unroll
        for (int j = 0; j < 3; j++) {
            int c = tid + 128*j;
            const float* xsr = xs + (size_t)(b*Nn + n) * Kk * Cc + c;
            float pv = 0.f;
            #pragma unroll
            for (int k = 0; k < Kk; k++) pv += xsr[(size_t)k*Cc];
            pv *= 0.2f;
            spp += pv*pv;
            sqp += qv[j]*pv;
        }
        float a = spp, d = sqp;
        #pragma unroll
        for (int o = 16; o; o >>= 1) {
            a += __shfl_xor_sync(0xffffffffu, a, o);
            d += __shfl_xor_sync(0xffffffffu, d, o);
        }
        if (lane == 0) { sm[wid] = a; sm[4 + wid] = d; }
        __syncthreads();
        if (tid == 0) {
            float PP = sm[0] + sm[1] + sm[2] + sm[3];
            float QP = sm[4] + sm[5] + sm[6] + sm[7];
            float denom = fmaxf(sqrtf(s_sqq), 1e-12f) * fmaxf(sqrtf(PP), 1e-12f);
            out[(size_t)Bb*Qq*Nn + (size_t)(b*Qq + q)*Nn + n] = TEMPF * QP / denom;
        }
        __syncthreads();
    }
}

// -----------------------------------------------------------------------------
extern "C" void kernel_launch(void* const* d_in, const int* in_sizes, int n_in,
                              void* d_out, int out_size) {
    const float *fs = nullptr, *fq = nullptr, *xs = nullptr, *xq = nullptr;
    for (int i = 0; i < n_in; i++) {
        long long sz = in_sizes[i];
        if      (sz == (long long)Bb*Nn*Kk*Tt*Cc) fs = (const float*)d_in[i];
        else if (sz == (long long)Bb*Qq*Tt*Cc)    fq = (const float*)d_in[i];
        else if (sz == (long long)Bb*Nn*Kk*Cc)    xs = (const float*)d_in[i];
        else if (sz == (long long)Bb*Qq*Cc)       xq = (const float*)d_in[i];
    }
    float* out = (float*)d_out;

    cudaFuncSetAttribute(sim_mma_kernel,
                         cudaFuncAttributeMaxDynamicSharedMemorySize, SMEM_BYTES);

    norm_q_kernel<<<(Bb*MQ + 3) / 4, 128>>>(fq);
    norm_s_kernel<<<(Bb*Nn*Ssz + 3) / 4, 128>>>(fs);
    sim_mma_kernel<<<dim3(MTILES, Bb*Nn), 256, SMEM_BYTES>>>();
    reduce_kernel<<<Bb*Qq*Nn, 64>>>(out);
    cls_kernel<<<Bb*Qq, 128>>>(xs, xq, out);
}

// round 17
// speedup vs baseline: 1.5950x; 1.0037x over previous
#include <cuda_runtime.h>
#include <cuda_fp16.h>
#include <math.h>
#include <stdint.h>

#define Bb 2
#define Nn 5
#define Kk 5
#define Qq 75
#define Tt 196
#define Cc 384
#define Ssz (Kk*Tt)        /* 980 */
#define MQ  (Qq*Tt)        /* 14700 rows per batch */
#define MQP 14848          /* padded M per batch (116*128) */
#define SSP 1024           /* padded S per (b,n) */
#define MTILES 115         /* per batch, tile 128 (115*128=14720 >= 14700) */
#define NTILES 8           /* 1024/128 */
#define KCH 6              /* 384/64 */
#define NSTEPS (NTILES*KCH)
#define RMSTRIDE 14720
#define TEMPF 10.0f

// dynamic smem: 3 pipeline stages of (A 16KB + B 16KB) + reduction scratch
#define STG_BYTES 32768
#define OFF_RED   98304
#define SMEM_BYTES (98304 + 1024 + 1024)

// ---------------- scratch (device globals: allocation-guard safe) ------------
__device__ __align__(16) __half g_Qh[Bb*MQP*Cc];      // [b][m(pad)][c] fp16 normalized
__device__ __align__(16) __half g_Sh[Bb*Nn*SSP*Cc];   // [bn][s(pad)][c]
__device__ __align__(16) float g_rowmax[Bb*Nn*RMSTRIDE];

// ---------------- helpers ----------------------------------------------------
__device__ __forceinline__ uint32_t smem_u32(const void* p) {
    uint32_t a;
    asm("{ .reg .u64 t; cvta.to.shared.u64 t, %1; cvt.u32.u64 %0, t; }" : "=r"(a) : "l"(p));
    return a;
}
__device__ __forceinline__ void cp16(uint32_t saddr, const void* g) {
    asm volatile("cp.async.cg.shared.global [%0], [%1], 16;" :: "r"(saddr), "l"(g));
}
__device__ __forceinline__ void cp_commit() {
    asm volatile("cp.async.commit_group;" ::: "memory");
}
__device__ __forceinline__ void cp_wait1() {
    asm volatile("cp.async.wait_group 1;" ::: "memory");
}
__device__ __forceinline__ void cp_wait0() {
    asm volatile("cp.async.wait_group 0;" ::: "memory");
}
__device__ __forceinline__ void ldsm4(uint32_t* r, uint32_t addr) {
    asm volatile("ldmatrix.sync.aligned.m8n8.x4.shared.b16 {%0,%1,%2,%3}, [%4];"
        : "=r"(r[0]), "=r"(r[1]), "=r"(r[2]), "=r"(r[3]) : "r"(addr));
}
__device__ __forceinline__ void mma16816(float* c, const uint32_t* a,
                                         uint32_t b0, uint32_t b1) {
    asm("mma.sync.aligned.m16n8k16.row.col.f32.f16.f16.f32 "
        "{%0,%1,%2,%3}, {%4,%5,%6,%7}, {%8,%9}, {%0,%1,%2,%3};"
        : "+f"(c[0]), "+f"(c[1]), "+f"(c[2]), "+f"(c[3])
        : "r"(a[0]), "r"(a[1]), "r"(a[2]), "r"(a[3]), "r"(b0), "r"(b1));
}
__device__ __forceinline__ uint32_t h2bits(float x, float y) {
    __half2 h = __floats2half2_rn(x, y);
    return *(uint32_t*)&h;
}

// ---------------- row L2 normalization -> fp16 -------------------------------
__device__ __forceinline__ void norm_rows_h(const float* __restrict__ in,
                                            __half* __restrict__ out,
                                            int rows, int inner, int pad_stride,
                                            float eps) {
    int row = blockIdx.x * 4 + (threadIdx.x >> 5);
    if (row >= rows) return;
    int lane = threadIdx.x & 31;
    int blk = row / inner, r = row - blk * inner;
    const float4* ip = (const float4*)(in + (size_t)row * Cc) + lane;
    float4 v0 = ip[0], v1 = ip[32], v2 = ip[64];
    float ss = v0.x*v0.x + v0.y*v0.y + v0.z*v0.z + v0.w*v0.w
             + v1.x*v1.x + v1.y*v1.y + v1.z*v1.z + v1.w*v1.w
             + v2.x*v2.x + v2.y*v2.y + v2.z*v2.z + v2.w*v2.w;
    #pragma unroll
    for (int o = 16; o; o >>= 1) ss += __shfl_xor_sync(0xffffffffu, ss, o);
    float s = 1.0f / fmaxf(sqrtf(ss), eps);
    uint2* op = (uint2*)(out + ((size_t)blk * pad_stride + r) * Cc);
    uint2 u0, u1, u2;
    u0.x = h2bits(v0.x*s, v0.y*s); u0.y = h2bits(v0.z*s, v0.w*s);
    u1.x = h2bits(v1.x*s, v1.y*s); u1.y = h2bits(v1.z*s, v1.w*s);
    u2.x = h2bits(v2.x*s, v2.y*s); u2.y = h2bits(v2.z*s, v2.w*s);
    op[lane] = u0; op[lane + 32] = u1; op[lane + 64] = u2;
}
__global__ void norm_q_kernel(const float* __restrict__ in) {
    norm_rows_h(in, g_Qh, Bb*MQ, MQ, MQP, 1e-8f);
}
__global__ void norm_s_kernel(const float* __restrict__ in) {
    norm_rows_h(in, g_Sh, Bb*Nn*Ssz, Ssz, SSP, 1e-8f);
}

// stage chunk (ntx, kcx) into pipeline stage stg: A 128x64h + B 128x64h, SW128
#define STAGE(stg, ntx, kcx) do {                                              \
    const __half* Asrc_ = Ag + (size_t)(kcx) * 64;                             \
    const __half* Bsrc_ = Sg + (size_t)((ntx) * 128) * Cc + (size_t)(kcx) * 64;\
    const uint32_t da_ = base + (uint32_t)(stg) * STG_BYTES;                   \
    const uint32_t db_ = da_ + 16384;                                          \
    _Pragma("unroll")                                                          \
    for (int it = 0; it < 8; it++) {                                           \
        int task = it * 128 + tid;                                             \
        int row = task >> 3, u = task & 7;                                     \
        cp16(da_ + row*128 + ((u*16) ^ ((row & 7) << 4)),                      \
             Asrc_ + (size_t)row * Cc + u*8);                                  \
    }                                                                          \
    _Pragma("unroll")                                                          \
    for (int it = 0; it < 8; it++) {                                           \
        int task = it * 128 + tid;                                             \
        int row = task >> 3, u = task & 7;                                     \
        cp16(db_ + row*128 + ((u*16) ^ ((row & 7) << 4)),                      \
             Bsrc_ + (size_t)row * Cc + u*8);                                  \
    }                                                                          \
    cp_commit();                                                               \
} while (0)

// ---------------- fp16 mma.sync GEMM + fused max-over-s ----------------------
// Grid (115 Mtiles, 10 bn), 128 threads = 4 warps as 2(m)x2(n), warp tile 64x64.
// CTA tile 128x128; 3-stage cp.async pipeline (lookahead 1), ONE sync/chunk.
// 97KB smem + ~190 regs -> 2 CTAs resident per SM for cross-CTA overlap.
__global__ __launch_bounds__(128, 2) void sim_mma_kernel() {
    extern __shared__ char dsm_raw[];
    const uint32_t base = (smem_u32(dsm_raw) + 1023) & ~1023u;

    const int tid = threadIdx.x;
    const int wid = tid >> 5, lane = tid & 31;
    const int wm = wid >> 1, wn = wid & 1;
    const int g = lane >> 2, q = lane & 3;
    const int lr = lane & 15;              // ldmatrix row-in-16
    const int lk = (lane >> 4) * 16;       // ldmatrix k-half byte offset
    const uint32_t sw = ((uint32_t)(lane & 7)) << 4;
    const int m0 = blockIdx.x * 128;
    const int bn = blockIdx.y;
    const int b  = bn / Nn;

    const __half* Ag = g_Qh + ((size_t)b * MQP + m0) * Cc;
    const __half* Sg = g_Sh + (size_t)bn * SSP * Cc;

    float* red = (float*)(dsm_raw + (base - smem_u32(dsm_raw)) + OFF_RED);

    float rmax[8];
    #pragma unroll
    for (int i = 0; i < 8; i++) rmax[i] = -1e30f;

    // ---- prologue: stage chunk 0 ----
    STAGE(0, 0, 0);

    for (int nt = 0; nt < NTILES; nt++) {
        float acc[4][8][4];
        #pragma unroll
        for (int fm = 0; fm < 4; fm++)
            #pragma unroll
            for (int fn = 0; fn < 8; fn++)
                #pragma unroll
                for (int j = 0; j < 4; j++) acc[fm][fn][j] = 0.f;

        #pragma unroll
        for (int kc = 0; kc < KCH; kc++) {
            const int step = nt * KCH + kc;
            const int s = step % 3;

            // ---- prefetch chunk step+1 (crosses n-tile boundary) ----
            {
                int kc1 = kc + 1, nt1 = nt;
                if (kc1 >= KCH) { kc1 -= KCH; nt1++; }
                if (nt1 < NTILES) {
                    STAGE((step + 1) % 3, nt1, kc1);
                    cp_wait1();
                } else {
                    cp_wait0();
                }
            }
            __syncthreads();   // single barrier per chunk

            // ---- compute: 4 k16 steps on stage s ----
            const uint32_t Abase = base + (uint32_t)s * STG_BYTES
                                 + (uint32_t)(wm*64 + lr) * 128;
            const uint32_t Bbase = base + (uint32_t)s * STG_BYTES + 16384
                                 + (uint32_t)(wn*64 + lr) * 128;
            #pragma unroll
            for (int kk = 0; kk < 4; kk++) {
                const uint32_t ko = ((uint32_t)(kk*32 + lk)) ^ sw;
                uint32_t afr[4][4], bfr[4][4];
                #pragma unroll
                for (int fm = 0; fm < 4; fm++)
                    ldsm4(afr[fm], Abase + fm*(16*128) + ko);
                #pragma unroll
                for (int fb = 0; fb < 4; fb++)
                    ldsm4(bfr[fb], Bbase + fb*(16*128) + ko);
                #pragma unroll
                for (int fm = 0; fm < 4; fm++)
                    #pragma unroll
                    for (int fn = 0; fn < 8; fn++)
                        mma16816(acc[fm][fn], afr[fm],
                                 bfr[fn >> 1][fn & 1], bfr[fn >> 1][(fn & 1) + 2]);
            }
        }

        // ---- tile done: fold into running row maxes (mask s >= Ssz) ----
        {
            const int s0 = nt * 128;
            #pragma unroll
            for (int fn = 0; fn < 8; fn++) {
                int sc = s0 + wn*64 + fn*8 + q*2;
                bool v0 = (sc < Ssz), v1 = (sc + 1 < Ssz);
                #pragma unroll
                for (int fm = 0; fm < 4; fm++) {
                    if (v0) {
                        rmax[fm*2+0] = fmaxf(rmax[fm*2+0], acc[fm][fn][0]);
                        rmax[fm*2+1] = fmaxf(rmax[fm*2+1], acc[fm][fn][2]);
                    }
                    if (v1) {
                        rmax[fm*2+0] = fmaxf(rmax[fm*2+0], acc[fm][fn][1]);
                        rmax[fm*2+1] = fmaxf(rmax[fm*2+1], acc[fm][fn][3]);
                    }
                }
            }
        }
    }

    // ---- reduce across the 4 quad lanes (same row), then across 2 n-warps ----
    #pragma unroll
    for (int i = 0; i < 8; i++) {
        float v = rmax[i];
        v = fmaxf(v, __shfl_xor_sync(0xffffffffu, v, 1));
        v = fmaxf(v, __shfl_xor_sync(0xffffffffu, v, 2));
        rmax[i] = v;
    }
    __syncthreads();
    if (q == 0) {
        #pragma unroll
        for (int fm = 0; fm < 4; fm++) {
            red[wn*128 + wm*64 + fm*16 + g]     = rmax[fm*2+0];
            red[wn*128 + wm*64 + fm*16 + g + 8] = rmax[fm*2+1];
        }
    }
    __syncthreads();
    {
        int m = m0 + tid;
        if (m < MQ) {
            float v = fmaxf(red[tid], red[128 + tid]);
            g_rowmax[(size_t)bn * RMSTRIDE + m] = v;
        }
    }
}

// ---------------- mean over t ------------------------------------------------
__global__ void reduce_kernel(float* __restrict__ out) {
    int idx = blockIdx.x;                 // (b*Qq+q)*Nn + n
    int n  = idx % Nn;
    int bq = idx / Nn;
    int b  = bq / Qq, q = bq % Qq;
    const float* rm = g_rowmax + (size_t)(b*Nn + n) * RMSTRIDE + (size_t)q * Tt;
    int tid = threadIdx.x;                // 64 threads
    float s = 0.f;
    for (int t = tid; t < Tt; t += 64) s += rm[t];
    #pragma unroll
    for (int o = 16; o; o >>= 1) s += __shfl_xor_sync(0xffffffffu, s, o);
    __shared__ float sm[2];
    if ((tid & 31) == 0) sm[tid >> 5] = s;
    __syncthreads();
    if (tid == 0) out[idx] = (sm[0] + sm[1]) / (float)Tt;
}

// ---------------- classifier branch ------------------------------------------
__global__ void cls_kernel(const float* __restrict__ xs,
                           const float* __restrict__ xq,
                           float* __restrict__ out) {
    int bq = blockIdx.x;
    int b = bq / Qq, q = bq % Qq;
    int tid = threadIdx.x;                 // 128 threads
    int lane = tid & 31, wid = tid >> 5;
    __shared__ float sm[8];
    __shared__ float s_sqq;

    const float* xqr = xq + (size_t)(b*Qq + q) * Cc;
    float qv[3];
    float sqq = 0.f;
    #pragma unroll
    for (int j = 0; j < 3; j++) { qv[j] = xqr[tid + 128*j]; sqq += qv[j]*qv[j]; }
    float r = sqq;
    #pragma unroll
    for (int o = 16; o; o >>= 1) r += __shfl_xor_sync(0xffffffffu, r, o);
    if (lane == 0) sm[wid] = r;
    __syncthreads();
    if (tid == 0) s_sqq = sm[0] + sm[1] + sm[2] + sm[3];
    __syncthreads();

    for (int n = 0; n < Nn; n++) {
        float spp = 0.f, sqp = 0.f;
        #pragma unroll
        for (int j = 0; j < 3; j++) {
            int c = tid + 128*j;
            const float* xsr = xs + (size_t)(b*Nn + n) * Kk * Cc + c;
            float pv = 0.f;
            #pragma unroll
            for (int k = 0; k < Kk; k++) pv += xsr[(size_t)k*Cc];
            pv *= 0.2f;
            spp += pv*pv;
            sqp += qv[j]*pv;
        }
        float a = spp, d = sqp;
        #pragma unroll
        for (int o = 16; o; o >>= 1) {
            a += __shfl_xor_sync(0xffffffffu, a, o);
            d += __shfl_xor_sync(0xffffffffu, d, o);
        }
        if (lane == 0) { sm[wid] = a; sm[4 + wid] = d; }
        __syncthreads();
        if (tid == 0) {
            float PP = sm[0] + sm[1] + sm[2] + sm[3];
            float QP = sm[4] + sm[5] + sm[6] + sm[7];
            float denom = fmaxf(sqrtf(s_sqq), 1e-12f) * fmaxf(sqrtf(PP), 1e-12f);
            out[(size_t)Bb*Qq*Nn + (size_t)(b*Qq + q)*Nn + n] = TEMPF * QP / denom;
        }
        __syncthreads();
    }
}

// -----------------------------------------------------------------------------
extern "C" void kernel_launch(void* const* d_in, const int* in_sizes, int n_in,
                              void* d_out, int out_size) {
    const float *fs = nullptr, *fq = nullptr, *xs = nullptr, *xq = nullptr;
    for (int i = 0; i < n_in; i++) {
        long long sz = in_sizes[i];
        if      (sz == (long long)Bb*Nn*Kk*Tt*Cc) fs = (const float*)d_in[i];
        else if (sz == (long long)Bb*Qq*Tt*Cc)    fq = (const float*)d_in[i];
        else if (sz == (long long)Bb*Nn*Kk*Cc)    xs = (const float*)d_in[i];
        else if (sz == (long long)Bb*Qq*Cc)       xq = (const float*)d_in[i];
    }
    float* out = (float*)d_out;

    cudaFuncSetAttribute(sim_mma_kernel,
                         cudaFuncAttributeMaxDynamicSharedMemorySize, SMEM_BYTES);

    norm_q_kernel<<<(Bb*MQ + 3) / 4, 128>>>(fq);
    norm_s_kernel<<<(Bb*Nn*Ssz + 3) / 4, 128>>>(fs);
    sim_mma_kernel<<<dim3(MTILES, Bb*Nn), 128, SMEM_BYTES>>>();
    reduce_kernel<<<Bb*Qq*Nn, 64>>>(out);
    cls_kernel<<<Bb*Qq, 128>>>(xs, xq, out);
}